// round 1
// baseline (speedup 1.0000x reference)
#include <cuda_runtime.h>
#include <cstdint>

// Problem: ERGCNLayer — out[n] = h[n] + sum_{k: dst[k]=n} ( h[src[k]]*weight[rel[k]] + e[k]*attention[rel[k]] )
// N=100000, E=1600000, D=64, R=200 (read from in_sizes at launch for safety).
//
// Inputs (metadata order):
//   d_in[0] = h         float32 [N, 64]
//   d_in[1] = e         float32 [E, 64]
//   d_in[2] = weight    float32 [R, 64]
//   d_in[3] = attention float32 [R, 64]
//   d_in[4] = src       int32   [E]
//   d_in[5] = dst       int32   [E]
//   d_in[6] = rel       int32   [E]
// Output: float32 [N, 64]

#define D 64
#define VEC_PER_ROW (D / 4)   // 16 float4 per row

// out = h (residual init), vectorized
__global__ void init_out_kernel(const float4* __restrict__ h4,
                                float4* __restrict__ out4,
                                int n4) {
    int i = blockIdx.x * blockDim.x + threadIdx.x;
    if (i < n4) out4[i] = h4[i];
}

// One float4 lane per thread; 16 threads cooperate on one edge.
__global__ void edge_scatter_kernel(const float4* __restrict__ h4,
                                    const float4* __restrict__ e4,
                                    const float4* __restrict__ w4,
                                    const float4* __restrict__ a4,
                                    const int* __restrict__ src,
                                    const int* __restrict__ dst,
                                    const int* __restrict__ rel,
                                    float* __restrict__ out,
                                    int E) {
    long long gid = (long long)blockIdx.x * blockDim.x + threadIdx.x;
    long long edge = gid >> 4;          // 16 threads per edge
    int lane = (int)(gid & 15);         // which float4 chunk of the 64-float row
    if (edge >= E) return;

    int s = src[edge];
    int d = dst[edge];
    int r = rel[edge];

    // All 64-byte-aligned coalesced float4 loads.
    float4 hv = h4[(long long)s * VEC_PER_ROW + lane];
    float4 wv = w4[(long long)r * VEC_PER_ROW + lane];
    float4 ev = e4[edge * VEC_PER_ROW + lane];
    float4 av = a4[(long long)r * VEC_PER_ROW + lane];

    float m0 = fmaf(hv.x, wv.x, ev.x * av.x);
    float m1 = fmaf(hv.y, wv.y, ev.y * av.y);
    float m2 = fmaf(hv.z, wv.z, ev.z * av.z);
    float m3 = fmaf(hv.w, wv.w, ev.w * av.w);

    float* dst_ptr = out + (long long)d * D + lane * 4;
    // Vector reduction (no return) — 1 instruction instead of 4 scalar atomics.
    asm volatile("red.global.add.v4.f32 [%0], {%1, %2, %3, %4};"
                 :: "l"(dst_ptr), "f"(m0), "f"(m1), "f"(m2), "f"(m3)
                 : "memory");
}

extern "C" void kernel_launch(void* const* d_in, const int* in_sizes, int n_in,
                              void* d_out, int out_size) {
    const float* h  = (const float*)d_in[0];
    const float* e  = (const float*)d_in[1];
    const float* w  = (const float*)d_in[2];
    const float* a  = (const float*)d_in[3];
    const int* src  = (const int*)d_in[4];
    const int* dst  = (const int*)d_in[5];
    const int* rel  = (const int*)d_in[6];
    float* out      = (float*)d_out;

    int E = in_sizes[4];               // element count of src
    int n4 = out_size / 4;             // number of float4 in output (= N*16)

    init_out_kernel<<<(n4 + 255) / 256, 256>>>((const float4*)h, (float4*)out, n4);

    long long total = (long long)E * 16;
    int threads = 256;
    long long blocks = (total + threads - 1) / threads;
    edge_scatter_kernel<<<(unsigned int)blocks, threads>>>(
        (const float4*)h, (const float4*)e, (const float4*)w, (const float4*)a,
        src, dst, rel, out, E);
}

// round 6
// speedup vs baseline: 1.0171x; 1.0171x over previous
#include <cuda_runtime.h>
#include <cstdint>

// ERGCNLayer: out[n] = h[n] + sum_{k: dst[k]=n} ( h[src[k]]*weight[rel[k]] + e[k]*attention[rel[k]] )
// N=100000, E=1600000, D=64, R=200
//
// Inputs (metadata order):
//   d_in[0]=h [N,64] f32, d_in[1]=e [E,64] f32, d_in[2]=weight [R,64] f32,
//   d_in[3]=attention [R,64] f32, d_in[4]=src [E] i32, d_in[5]=dst [E] i32, d_in[6]=rel [E] i32
// Output: float32 [N,64]

#define D 64
#define VEC_PER_ROW (D / 4)   // 16 float4 per row
#define TPE 8                 // threads per edge (each thread: 2 float4 = 32B of the row)
#define EPT 2                 // edges per thread

// out = h (residual init)
__global__ void init_out_kernel(const float4* __restrict__ h4,
                                float4* __restrict__ out4,
                                int n4) {
    int i = blockIdx.x * blockDim.x + threadIdx.x;
    if (i < n4) out4[i] = h4[i];
}

__global__ void __launch_bounds__(256)
edge_scatter_kernel(const float4* __restrict__ h4,
                    const float4* __restrict__ e4,
                    const float4* __restrict__ w4,
                    const float4* __restrict__ a4,
                    const int* __restrict__ src,
                    const int* __restrict__ dst,
                    const int* __restrict__ rel,
                    float* __restrict__ out,
                    int E) {
    long long tgid  = (long long)blockIdx.x * blockDim.x + threadIdx.x;
    int       sub   = (int)(tgid & (TPE - 1));        // which 32B chunk of the 64-float row
    long long ebase = (tgid >> 3) * EPT;              // first edge of this thread's batch

    // ---- Phase 1: independent loads — indices + streaming e for all EPT edges ----
    int s[EPT], d[EPT], r[EPT];
    float4 ev0[EPT], ev1[EPT];
    bool valid[EPT];
#pragma unroll
    for (int k = 0; k < EPT; k++) {
        long long edge = ebase + k;
        valid[k] = edge < E;
        long long ce = valid[k] ? edge : 0;
        s[k] = __ldg(src + ce);
        d[k] = __ldg(dst + ce);
        r[k] = __ldg(rel + ce);
        // e is touched exactly once -> streaming, keep h/out resident in L2
        ev0[k] = __ldcs(e4 + ce * VEC_PER_ROW + sub);
        ev1[k] = __ldcs(e4 + ce * VEC_PER_ROW + sub + TPE);
    }

    // ---- Phase 2: dependent gathers (h is L2-resident; w/a tiny & hot) ----
    float4 hv0[EPT], hv1[EPT], wv0[EPT], wv1[EPT], av0[EPT], av1[EPT];
#pragma unroll
    for (int k = 0; k < EPT; k++) {
        long long hb = (long long)s[k] * VEC_PER_ROW;
        long long rb = (long long)r[k] * VEC_PER_ROW;
        hv0[k] = __ldg(h4 + hb + sub);
        hv1[k] = __ldg(h4 + hb + sub + TPE);
        wv0[k] = __ldg(w4 + rb + sub);
        wv1[k] = __ldg(w4 + rb + sub + TPE);
        av0[k] = __ldg(a4 + rb + sub);
        av1[k] = __ldg(a4 + rb + sub + TPE);
    }

    // ---- Phase 3: compute + vector reductions ----
#pragma unroll
    for (int k = 0; k < EPT; k++) {
        if (!valid[k]) continue;
        float m0x = fmaf(hv0[k].x, wv0[k].x, ev0[k].x * av0[k].x);
        float m0y = fmaf(hv0[k].y, wv0[k].y, ev0[k].y * av0[k].y);
        float m0z = fmaf(hv0[k].z, wv0[k].z, ev0[k].z * av0[k].z);
        float m0w = fmaf(hv0[k].w, wv0[k].w, ev0[k].w * av0[k].w);
        float m1x = fmaf(hv1[k].x, wv1[k].x, ev1[k].x * av1[k].x);
        float m1y = fmaf(hv1[k].y, wv1[k].y, ev1[k].y * av1[k].y);
        float m1z = fmaf(hv1[k].z, wv1[k].z, ev1[k].z * av1[k].z);
        float m1w = fmaf(hv1[k].w, wv1[k].w, ev1[k].w * av1[k].w);

        float* p0 = out + (long long)d[k] * D + sub * 4;
        float* p1 = p0 + TPE * 4;
        asm volatile("red.global.add.v4.f32 [%0], {%1, %2, %3, %4};"
                     :: "l"(p0), "f"(m0x), "f"(m0y), "f"(m0z), "f"(m0w) : "memory");
        asm volatile("red.global.add.v4.f32 [%0], {%1, %2, %3, %4};"
                     :: "l"(p1), "f"(m1x), "f"(m1y), "f"(m1z), "f"(m1w) : "memory");
    }
}

extern "C" void kernel_launch(void* const* d_in, const int* in_sizes, int n_in,
                              void* d_out, int out_size) {
    const float* h  = (const float*)d_in[0];
    const float* e  = (const float*)d_in[1];
    const float* w  = (const float*)d_in[2];
    const float* a  = (const float*)d_in[3];
    const int* src  = (const int*)d_in[4];
    const int* dst  = (const int*)d_in[5];
    const int* rel  = (const int*)d_in[6];
    float* out      = (float*)d_out;

    int E  = in_sizes[4];
    int n4 = out_size / 4;

    init_out_kernel<<<(n4 + 255) / 256, 256>>>((const float4*)h, (float4*)out, n4);

    long long groups = ((long long)E + EPT - 1) / EPT;
    long long total  = groups * TPE;
    int threads = 256;
    long long blocks = (total + threads - 1) / threads;
    edge_scatter_kernel<<<(unsigned int)blocks, threads>>>(
        (const float4*)h, (const float4*)e, (const float4*)w, (const float4*)a,
        src, dst, rel, out, E);
}